// round 6
// baseline (speedup 1.0000x reference)
#include <cuda_runtime.h>
#include <cstdint>

#define Bn 64
#define Tn 64
#define Dn 64
#define Pn 63
typedef unsigned long long ull;

// ---------------- device scratch ----------------
__device__ float g_emb[Tn * Bn * 128];            // [t][b][e]
__device__ ull   g_embP[Tn * 32 * 128];           // [t][rpg][e] batch-row pairs packed
__device__ ull   g_giP[64 * 2 * 32 * 3 * 128];    // [t][gru][rpg][gate][k]
__device__ float g_WiaT[128 * 384];               // [e][u]
__device__ float g_WibT[128 * 384];
__device__ float g_WhP2[8 * 12288];               // tile tl: [li][ihalf][gru][(wr,wz)x128 | wn x128]
__device__ float g_WbT[128 * 128];                // [i][e]
__device__ float g_WembT[64 * 128];               // [d][e]
__device__ float g_WoWemb[128 * 64];              // [e][d]

// ---------------- f32x2 helpers ----------------
__device__ __forceinline__ ull pack2(float x, float y) {
    ull r; asm("mov.b64 %0, {%1,%2};" : "=l"(r) : "f"(x), "f"(y)); return r;
}
__device__ __forceinline__ float2 unpack2(ull v) {
    float2 r; asm("mov.b64 {%0,%1}, %2;" : "=f"(r.x), "=f"(r.y) : "l"(v)); return r;
}
__device__ __forceinline__ ull fma2(ull a, ull b, ull c) {
    ull d; asm("fma.rn.f32x2 %0, %1, %2, %3;" : "=l"(d) : "l"(a), "l"(b), "l"(c)); return d;
}
__device__ __forceinline__ ull add2(ull a, ull b) {
    ull d; asm("add.rn.f32x2 %0, %1, %2;" : "=l"(d) : "l"(a), "l"(b)); return d;
}
__device__ __forceinline__ ull mul2(ull a, ull b) {
    ull d; asm("mul.rn.f32x2 %0, %1, %2;" : "=l"(d) : "l"(a), "l"(b)); return d;
}
__device__ __forceinline__ float sigmoidf_(float v) {
    return __fdividef(1.f, 1.f + __expf(-v));
}
__device__ __forceinline__ float tanhfast(float v) {
    float e = __expf(2.f * v);
    return 1.f - __fdividef(2.f, e + 1.f);
}
__device__ __forceinline__ float gru_step(float ir, float iz, float in_,
                                          float hr, float hz, float hn, float h) {
    float r = sigmoidf_(ir + hr);
    float z = sigmoidf_(iz + hz);
    float n = tanhfast(in_ + r * hn);
    return n + z * (h - n);
}

// ---------------- cp.async helpers ----------------
__device__ __forceinline__ void cp16(uint32_t dst, const void* src) {
    asm volatile("cp.async.cg.shared.global [%0], [%1], 16;\n" :: "r"(dst), "l"(src));
}
__device__ __forceinline__ void cp_commit() {
    asm volatile("cp.async.commit_group;\n" ::: "memory");
}
__device__ __forceinline__ void cp_wait1() {
    asm volatile("cp.async.wait_group 1;\n" ::: "memory");
}

// ---------------- prep ----------------
__global__ void prep_transpose(const float* __restrict__ Wh_a,
                               const float* __restrict__ Wh_b,
                               const float* __restrict__ Wi_a,
                               const float* __restrict__ Wi_b,
                               const float* __restrict__ Wb,
                               const float* __restrict__ W_emb,
                               const float* __restrict__ Wo) {
    int idx = blockIdx.x * blockDim.x + threadIdx.x;
    int stride = gridDim.x * blockDim.x;
    for (int n = idx; n < 128 * 384; n += stride) {
        int u = n % 384, i = n / 384;
        g_WiaT[n] = Wi_a[u * 128 + i];
        g_WibT[n] = Wi_b[u * 128 + i];
    }
    // WhP2: tile tl holds i-rows {tl*8..tl*8+7} for ihalf=0 and {64+tl*8..} for ihalf=1
    for (int n = idx; n < 128 * 256; n += stride) {
        int i = n >> 8;
        int rem = n & 255;
        int gru = rem >> 7;
        int k = rem & 127;
        const float* Wh = gru ? Wh_b : Wh_a;
        float wr = Wh[(0   + k) * 128 + i];
        float wz = Wh[(128 + k) * 128 + i];
        float wn = Wh[(256 + k) * 128 + i];
        int tl = (i & 63) >> 3, li = i & 7, ihalf = i >> 6;
        int base = tl * 12288 + ((li * 2 + ihalf) * 2 + gru) * 384;
        g_WhP2[base + 2 * k]     = wr;
        g_WhP2[base + 2 * k + 1] = wz;
        g_WhP2[base + 256 + k]   = wn;
    }
    for (int n = idx; n < 128 * 128; n += stride) {
        int e = n % 128, i = n / 128;
        g_WbT[n] = Wb[e * 128 + i];
    }
    for (int n = idx; n < 64 * 128; n += stride) {
        int e = n % 128, d = n / 128;
        g_WembT[n] = W_emb[e * 64 + d];
    }
    for (int n = idx; n < 128 * 64; n += stride) {
        int d = n % 64, e = n / 64;
        g_WoWemb[n] = Wo[e] * W_emb[e * 64 + d];
    }
}

// ---------------- emb ----------------
__global__ void emb_kernel(const float* __restrict__ x, const float* __restrict__ b_emb) {
    __shared__ float xs[64];
    int tb = blockIdx.x;
    int t_ = tb >> 6, b = tb & 63;
    int e = threadIdx.x;
    if (e < 64) xs[e] = x[((size_t)b * Tn + t_) * Dn + e];
    __syncthreads();
    float acc = 0.f;
#pragma unroll 8
    for (int d = 0; d < 64; ++d) acc = fmaf(g_WembT[d * 128 + e], xs[d], acc);
    g_emb[(size_t)tb * 128 + e] = acc + b_emb[e];
}

// ---------------- gi (packed) + emb packing ----------------
__global__ void gi_kernel(const float* __restrict__ bi_a, const float* __restrict__ bi_b) {
    __shared__ float es[128];
    int tb = blockIdx.x;
    int t_ = tb >> 6, b = tb & 63;
    int t = threadIdx.x;
    if (t < 128) es[t] = g_emb[(size_t)tb * 128 + t];
    __syncthreads();
    float* gf = (float*)g_giP;
    for (int u = t; u < 768; u += 256) {
        const float* WT;
        const float* bi;
        int gru, uu;
        if (u < 384) { WT = g_WiaT; bi = bi_a; gru = 0; uu = u; }
        else         { WT = g_WibT; bi = bi_b; gru = 1; uu = u - 384; }
        float acc = 0.f;
#pragma unroll 8
        for (int e = 0; e < 128; ++e) acc = fmaf(WT[e * 384 + uu], es[e], acc);
        int gate = uu >> 7, k = uu & 127;
        size_t ullIdx = (((size_t)(t_ * 2 + gru) * 32 + (b >> 1)) * 3 + gate) * 128 + k;
        gf[ullIdx * 2 + (b & 1)] = acc + bi[uu];
    }
    // pack emb batch-row pairs (b even blocks do the pair (b, b+1))
    if ((b & 1) == 0 && t < 128) {
        g_embP[((size_t)t_ * 32 + (b >> 1)) * 128 + t] =
            pack2(g_emb[(size_t)tb * 128 + t], g_emb[(size_t)(tb + 1) * 128 + t]);
    }
}

// ---------------- main persistent kernel ----------------
// grid 128 = 32 prefix-pairs x 4 batch-chunks of 16 rows; 512 threads.
#define RING_BYTES 147456              // 3 slots x 48KB
#define SHH_OFF    147456              // ull [2][2][128][8] = 32768
#define BETA_OFF   180224              // ull [8][128] = 8192
#define RED_OFF    188416              // ull [6*512] = 24576
#define SCAL_OFF   212992              // floats (see layout below)
#define SMEM_TOTAL 213824

__global__ __launch_bounds__(512, 1) void retain_main(
    const float* __restrict__ x,
    const float* __restrict__ bh_a, const float* __restrict__ bh_b,
    const float* __restrict__ Wa, const float* __restrict__ ba,
    const float* __restrict__ bb, const float* __restrict__ Wo,
    const float* __restrict__ bo, int nq, float* __restrict__ out) {

    extern __shared__ char dsm[];
    float* smw = (float*)dsm;
    ull (*sh_h)[2][128][8] = (ull (*)[2][128][8])(dsm + SHH_OFF);
    ull (*sh_betaP)[128]   = (ull (*)[128])(dsm + BETA_OFF);
    ull* red               = (ull*)(dsm + RED_OFF);
    float* sh_preA  = (float*)(dsm + SCAL_OFF);    // [16]
    float* sh_m     = sh_preA + 16;                // [16]
    float* sh_l     = sh_preA + 32;                // [16]
    ull*   sh_scaleP = (ull*)(sh_preA + 48);       // [8]
    ull*   sh_wP     = (ull*)(sh_preA + 64);       // [8]
    float* sh_Wa    = sh_preA + 80;                // [128]

    const int t = threadIdx.x;
    const int pb = blockIdx.x >> 2;
    const int b0 = (blockIdx.x & 3) * 16;

    const int ihalf = t >> 8;          // i-range half (warp-uniform)
    const int gru = (t >> 7) & 1;
    const int k = t & 127;             // hidden / e index
    const int grpB = t >> 7;           // 0..3 (= ihalf*2+gru)
    const int d_ = t & 63;
    const int rp6 = t >> 6;            // 0..7 row-pair for e-chain/gacc
    const int warp = t >> 5;
    const int lane = t & 31;
    const int mb = ihalf * 4;
    const int pt = t ^ 256;

    const float* bh = gru ? bh_b : bh_a;
    const float bhr = bh[k], bhz = bh[128 + k], bhn = bh[256 + k];
    const float ba0 = ba[0], bbk = bb[k];
    const int base = Pn - nq;

    if (t < 128) sh_Wa[t] = Wa[t];

    const bool seg2 = (pb < 31) && (pb >= base);
    const int totalSteps = (63 - pb) + (seg2 ? pb + 1 : 0);
    const int totalTiles = 11 * totalSteps;

    uint32_t smw32 = (uint32_t)__cvta_generic_to_shared(dsm);
    int issIdx = 0, issM = 0, issSlot = 0, consSlot = 0;

#define ISSUE_ONE() do {                                                        \
        const char* _src; int _bytes;                                           \
        if (issM < 8)       { _src = (const char*)g_WhP2 + issM * 49152; _bytes = 49152; } \
        else if (issM == 8) { _src = (const char*)g_WbT;            _bytes = 32768; } \
        else if (issM == 9) { _src = (const char*)g_WbT + 32768;    _bytes = 32768; } \
        else                { _src = (const char*)g_WoWemb;         _bytes = 32768; } \
        uint32_t _d = smw32 + (uint32_t)issSlot * 49152u;                        \
        for (int _o = t * 16; _o < _bytes; _o += 8192) cp16(_d + _o, _src + _o); \
        cp_commit();                                                             \
        ++issIdx; if (++issM == 11) issM = 0; if (++issSlot == 3) issSlot = 0;   \
    } while (0)

#define ADVANCE() do {                                                          \
        cp_wait1(); __syncthreads();                                            \
        if (issIdx < totalTiles) { ISSUE_ONE(); }                               \
    } while (0)

    ISSUE_ONE();
    ISSUE_ONE();

    for (int seg = 0; seg < 2; ++seg) {
        const int p = seg ? pb : 62 - pb;
        if (seg && !seg2) break;

        for (int n = t; n < 2 * 128 * 8; n += 512)
            ((ull*)sh_h[0])[n] = 0ull;
        if (t < 16) { sh_m[t] = -1e30f; sh_l[t] = 0.f; }
        ull cacc[2] = {0ull, 0ull};
        ull gacc = 0ull;
        __syncthreads();

        for (int s = 0; s <= p; ++s) {
            const int j = p - s;
            const int cb = s & 1;
            const ull (*cur)[8]  = sh_h[cb][gru];
            ull (*nxtg)[8]       = sh_h[cb ^ 1][gru];
            const ull (*nxtA)[8] = sh_h[cb ^ 1][0];
            const ull (*nxtB)[8] = sh_h[cb ^ 1][1];

            // ---- phase 1: partial gh over this half's 64 i, all 8 row-pairs ----
            ull aR[8], aZ[8], aN[8];
#pragma unroll
            for (int r = 0; r < 8; ++r) { aR[r] = 0ull; aZ[r] = 0ull; aN[r] = 0ull; }

#pragma unroll 1
            for (int tl = 0; tl < 8; ++tl) {
                ADVANCE();
                const float* wrow = smw + (size_t)consSlot * 12288 + (ihalf * 2 + gru) * 384;
                consSlot = (consSlot + 1) == 3 ? 0 : consSlot + 1;
                const ull* hrow = &cur[ihalf * 64 + tl * 8][0];
#pragma unroll
                for (int li = 0; li < 8; ++li) {
                    float2 rz = *(const float2*)(wrow + 2 * k);
                    float wn = wrow[256 + k];
                    ull wr2 = pack2(rz.x, rz.x), wz2 = pack2(rz.y, rz.y), wn2 = pack2(wn, wn);
                    const ulonglong2* hp = reinterpret_cast<const ulonglong2*>(hrow);
                    ulonglong2 hA = hp[0], hB = hp[1], hC = hp[2], hD = hp[3];
                    aR[0] = fma2(wr2, hA.x, aR[0]); aZ[0] = fma2(wz2, hA.x, aZ[0]); aN[0] = fma2(wn2, hA.x, aN[0]);
                    aR[1] = fma2(wr2, hA.y, aR[1]); aZ[1] = fma2(wz2, hA.y, aZ[1]); aN[1] = fma2(wn2, hA.y, aN[1]);
                    aR[2] = fma2(wr2, hB.x, aR[2]); aZ[2] = fma2(wz2, hB.x, aZ[2]); aN[2] = fma2(wn2, hB.x, aN[2]);
                    aR[3] = fma2(wr2, hB.y, aR[3]); aZ[3] = fma2(wz2, hB.y, aZ[3]); aN[3] = fma2(wn2, hB.y, aN[3]);
                    aR[4] = fma2(wr2, hC.x, aR[4]); aZ[4] = fma2(wz2, hC.x, aZ[4]); aN[4] = fma2(wn2, hC.x, aN[4]);
                    aR[5] = fma2(wr2, hC.y, aR[5]); aZ[5] = fma2(wz2, hC.y, aZ[5]); aN[5] = fma2(wn2, hC.y, aN[5]);
                    aR[6] = fma2(wr2, hD.x, aR[6]); aZ[6] = fma2(wz2, hD.x, aZ[6]); aN[6] = fma2(wn2, hD.x, aN[6]);
                    aR[7] = fma2(wr2, hD.y, aR[7]); aZ[7] = fma2(wz2, hD.y, aZ[7]); aN[7] = fma2(wn2, hD.y, aN[7]);
                    wrow += 1536;
                    hrow += 8;
                }
            }

            // ---- cross-half reduction (mine -> aX[0..3], other's -> aX[4..7]) ----
            if (ihalf) {
#pragma unroll
                for (int c = 0; c < 4; ++c) {
                    ull tmp;
                    tmp = aR[c]; aR[c] = aR[4 + c]; aR[4 + c] = tmp;
                    tmp = aZ[c]; aZ[c] = aZ[4 + c]; aZ[4 + c] = tmp;
                    tmp = aN[c]; aN[c] = aN[4 + c]; aN[4 + c] = tmp;
                }
            }
            // wave A
            red[t] = aR[4]; red[512 + t] = aR[5]; red[1024 + t] = aR[6]; red[1536 + t] = aR[7];
            red[2048 + t] = aZ[4]; red[2560 + t] = aZ[5];
            __syncthreads();
            aR[0] = add2(aR[0], red[pt]);
            aR[1] = add2(aR[1], red[512 + pt]);
            aR[2] = add2(aR[2], red[1024 + pt]);
            aR[3] = add2(aR[3], red[1536 + pt]);
            aZ[0] = add2(aZ[0], red[2048 + pt]);
            aZ[1] = add2(aZ[1], red[2560 + pt]);
            __syncthreads();
            // wave B
            red[t] = aZ[6]; red[512 + t] = aZ[7];
            red[1024 + t] = aN[4]; red[1536 + t] = aN[5];
            red[2048 + t] = aN[6]; red[2560 + t] = aN[7];
            __syncthreads();
            aZ[2] = add2(aZ[2], red[pt]);
            aZ[3] = add2(aZ[3], red[512 + pt]);
            aN[0] = add2(aN[0], red[1024 + pt]);
            aN[1] = add2(aN[1], red[1536 + pt]);
            aN[2] = add2(aN[2], red[2048 + pt]);
            aN[3] = add2(aN[3], red[2560 + pt]);

            // ---- phase 2: GRU update, rps mb..mb+3 at hidden k ----
            {
                const ull* gb = g_giP + (((size_t)(j * 2 + gru) * 32 + (b0 >> 1) + mb) * 3) * 128 + k;
                const ulonglong2* hop = (const ulonglong2*)(cur[k] + mb);
                ulonglong2 ho01 = hop[0], ho23 = hop[1];
                ull hn_[4];
#pragma unroll
                for (int c = 0; c < 4; ++c) {
                    float2 gr = unpack2(gb[(size_t)c * 384]);
                    float2 gz = unpack2(gb[(size_t)c * 384 + 128]);
                    float2 gn = unpack2(gb[(size_t)c * 384 + 256]);
                    float2 hr = unpack2(aR[c]);
                    float2 hz = unpack2(aZ[c]);
                    float2 hnn = unpack2(aN[c]);
                    float2 ho = unpack2(c < 2 ? (c == 0 ? ho01.x : ho01.y)
                                              : (c == 2 ? ho23.x : ho23.y));
                    float hx = gru_step(gr.x, gz.x, gn.x,
                                        hr.x + bhr, hz.x + bhz, hnn.x + bhn, ho.x);
                    float hy = gru_step(gr.y, gz.y, gn.y,
                                        hr.y + bhr, hz.y + bhz, hnn.y + bhn, ho.y);
                    hn_[c] = pack2(hx, hy);
                }
                ulonglong2* dst = (ulonglong2*)(nxtg[k] + mb);
                dst[0] = make_ulonglong2(hn_[0], hn_[1]);
                dst[1] = make_ulonglong2(hn_[2], hn_[3]);
            }

            // ---- phase 3a: beta (grpB -> rp {2grpB, 2grpB+1}, full i) + preA ----
            ull bacc0 = 0ull, bacc1 = 0ull;
            {
                ADVANCE();   // tile 8: WbT rows i<64 (sync orders phase-2 writes)
                const float* wbb = smw + (size_t)consSlot * 12288;
                consSlot = (consSlot + 1) == 3 ? 0 : consSlot + 1;
#pragma unroll 2
                for (int i = 0; i < 64; ++i) {
                    float wv = wbb[i * 128 + k];
                    ull wb2 = pack2(wv, wv);
                    ulonglong2 hv = *(const ulonglong2*)(nxtB[i] + 2 * grpB);
                    bacc0 = fma2(wb2, hv.x, bacc0);
                    bacc1 = fma2(wb2, hv.y, bacc1);
                }
            }
            {   // preA: warp w handles row w
                float part = 0.f;
#pragma unroll
                for (int ii = 0; ii < 4; ++ii) {
                    int i = lane + 32 * ii;
                    float2 hv = unpack2(nxtA[i][warp >> 1]);
                    part = fmaf(sh_Wa[i], (warp & 1) ? hv.y : hv.x, part);
                }
#pragma unroll
                for (int o = 16; o; o >>= 1)
                    part += __shfl_xor_sync(0xffffffffu, part, o);
                if (lane == 0) sh_preA[warp] = fmaf(0.5f, part, ba0);
            }
            {
                ADVANCE();   // tile 9: WbT rows i>=64
                const float* wbb = smw + (size_t)consSlot * 12288;
                consSlot = (consSlot + 1) == 3 ? 0 : consSlot + 1;
#pragma unroll 2
                for (int i = 0; i < 64; ++i) {
                    float wv = wbb[i * 128 + k];
                    ull wb2 = pack2(wv, wv);
                    ulonglong2 hv = *(const ulonglong2*)(nxtB[64 + i] + 2 * grpB);
                    bacc0 = fma2(wb2, hv.x, bacc0);
                    bacc1 = fma2(wb2, hv.y, bacc1);
                }
                float2 v0 = unpack2(bacc0), v1 = unpack2(bacc1);
                sh_betaP[2 * grpB][k] =
                    pack2(tanhfast(fmaf(0.5f, v0.x, bbk)), tanhfast(fmaf(0.5f, v0.y, bbk)));
                sh_betaP[2 * grpB + 1][k] =
                    pack2(tanhfast(fmaf(0.5f, v1.x, bbk)), tanhfast(fmaf(0.5f, v1.y, bbk)));
            }

            // ---- phase 3b: softmax scalars + e_chain ----
            ull ea = 0ull;
            {
                ADVANCE();   // tile 10: WoWemb (sync orders betaP + preA)
                const float* wco = smw + (size_t)consSlot * 12288;
                consSlot = (consSlot + 1) == 3 ? 0 : consSlot + 1;
                if (t < 8) {
                    float pa0 = sh_preA[2 * t], pa1 = sh_preA[2 * t + 1];
                    float m0 = sh_m[2 * t], m1 = sh_m[2 * t + 1];
                    float mn0 = fmaxf(m0, pa0), mn1 = fmaxf(m1, pa1);
                    float sc0 = __expf(m0 - mn0), sc1 = __expf(m1 - mn1);
                    float w0 = __expf(pa0 - mn0), w1 = __expf(pa1 - mn1);
                    sh_l[2 * t] = sh_l[2 * t] * sc0 + w0;
                    sh_l[2 * t + 1] = sh_l[2 * t + 1] * sc1 + w1;
                    sh_m[2 * t] = mn0; sh_m[2 * t + 1] = mn1;
                    sh_scaleP[t] = pack2(sc0, sc1);
                    sh_wP[t] = pack2(w0, w1);
                }
                const ull* bp = sh_betaP[rp6];
                const float* wc0 = wco + d_;
#pragma unroll 2
                for (int e = 0; e < 128; ++e) {
                    float wc = wc0[e * 64];
                    ea = fma2(pack2(wc, wc), bp[e], ea);
                }
            }
            __syncthreads();   // order sh_scaleP/sh_wP before 3c

            // ---- phase 3c: accumulators ----
            {
                // context: thread (grpB, k) handles rp {2grpB, 2grpB+1}
                const ull* ebp = g_embP + ((size_t)j * 32 + (b0 >> 1) + 2 * grpB) * 128 + k;
#pragma unroll
                for (int cc = 0; cc < 2; ++cc) {
                    int rp = 2 * grpB + cc;
                    ull prod = mul2(mul2(sh_wP[rp], sh_betaP[rp][k]), ebp[(size_t)cc * 128]);
                    cacc[cc] = fma2(sh_scaleP[rp], cacc[cc], prod);
                }
                // interpretability: thread (rp6, d_) handles rows (2rp6, 2rp6+1)
                const float* xb = x + ((size_t)(b0 + 2 * rp6) * Tn + j) * Dn + d_;
                ull xp = pack2(xb[0], xb[(size_t)Tn * Dn]);
                gacc = fma2(sh_scaleP[rp6], gacc, mul2(mul2(sh_wP[rp6], ea), xp));
            }
        } // steps

        // ---- finalize ----
        __syncthreads();
        if (p >= base) {
            const int q = p - base;
            sh_betaP[2 * grpB][k] = cacc[0];
            sh_betaP[2 * grpB + 1][k] = cacc[1];
            __syncthreads();

            if (t < 16) {
                float sum = 0.f;
                const ull* Crow = sh_betaP[t >> 1];
                const bool hi = (t & 1);
#pragma unroll 8
                for (int e = 0; e < 128; ++e) {
                    float2 v = unpack2(Crow[e]);
                    sum = fmaf(Wo[e], hi ? v.y : v.x, sum);
                }
                out[(size_t)(b0 + t) * nq + q] = __fdividef(sum, sh_l[t]) + bo[0];
            }
            {
                float inv = __fdividef(1.f, (float)(p + 1));
                size_t wbase = (size_t)64 * nq;
                float2 gv = unpack2(gacc);
                float l0 = sh_l[2 * rp6], l1 = sh_l[2 * rp6 + 1];
                out[wbase + ((size_t)(b0 + 2 * rp6) * nq + q) * 64 + d_] =
                    __fdividef(gv.x, l0) * inv;
                out[wbase + ((size_t)(b0 + 2 * rp6 + 1) * nq + q) * 64 + d_] =
                    __fdividef(gv.y, l1) * inv;
            }
        }
        __syncthreads();
    } // segments
#undef ADVANCE
#undef ISSUE_ONE
}

// ---------------- launch ----------------
extern "C" void kernel_launch(void* const* d_in, const int* in_sizes, int n_in,
                              void* d_out, int out_size) {
    const float* x     = (const float*)d_in[0];
    const float* W_emb = (const float*)d_in[1];
    const float* b_emb = (const float*)d_in[2];
    const float* Wi_a  = (const float*)d_in[3];
    const float* Wh_a  = (const float*)d_in[4];
    const float* bi_a  = (const float*)d_in[5];
    const float* bh_a  = (const float*)d_in[6];
    const float* Wi_b  = (const float*)d_in[7];
    const float* Wh_b  = (const float*)d_in[8];
    const float* bi_b  = (const float*)d_in[9];
    const float* bh_b  = (const float*)d_in[10];
    const float* Wa    = (const float*)d_in[11];
    const float* ba    = (const float*)d_in[12];
    const float* Wb    = (const float*)d_in[13];
    const float* bb    = (const float*)d_in[14];
    const float* Wo    = (const float*)d_in[15];
    const float* bo    = (const float*)d_in[16];
    float* out = (float*)d_out;

    int nq = out_size / (64 * 65);

    static int smem_set = 0;
    if (!smem_set) {
        cudaFuncSetAttribute(retain_main,
                             cudaFuncAttributeMaxDynamicSharedMemorySize, SMEM_TOTAL);
        smem_set = 1;
    }

    prep_transpose<<<96, 256>>>(Wh_a, Wh_b, Wi_a, Wi_b, Wb, W_emb, Wo);
    emb_kernel<<<Tn * Bn, 128>>>(x, b_emb);
    gi_kernel<<<Tn * Bn, 256>>>(bi_a, bi_b);
    retain_main<<<128, 512, SMEM_TOTAL>>>(x, bh_a, bh_b, Wa, ba, bb, Wo, bo, nq, out);
}